// round 1
// baseline (speedup 1.0000x reference)
#include <cuda_runtime.h>
#include <cuda_bf16.h>

// ---------------------------------------------------------------------------
// BiGRIL collapsed forward.
//
// Key fact: h == 0 everywhere, so the whole network up to the PReLU is affine
// in (x1, mask, s1, s2, colsum[n]) where
//   x1  = mask ? x : b_fs[0]
//   s1[b,m,t] = sum_n adj[n,m] * x1[b,n,t]
//   s2[b,m,t] = sum_n adj[n,m] * mask[b,n,t]
//   cs[m]     = sum_n adj[n,m]
// o_pre[o] = C0[o]*x1 + C1[o]*m + C2[o]*s1 + C3[o]*s2 + C4[o]*cs + C5[o]
// out      = MLP( W_ro . prelu(o_pre) + b_ro )
// ---------------------------------------------------------------------------

#define Bdim 8
#define Cdim 1
#define Ndim 1024
#define Tdim 64
#define Hdim 64
#define NCOLS 512            // B*T
#define TOTAL (Bdim*Ndim*Tdim)

// scratch (static device memory; no allocations)
__device__ float g_S[Ndim * 1024];   // [m][j], j<512: s1, j>=512: s2  (4 MB)
__device__ float g_cs[Ndim];
__device__ float g_C[6 * Hdim];

// ---------------------------------------------------------------------------
// Kernel 1: fold weights into coefficient vectors C0..C5; zero g_cs.
// one block, 64 threads.
// ---------------------------------------------------------------------------
__global__ void coeff_kernel(const float* __restrict__ W_in,
                             const float* __restrict__ b_in,
                             const float* __restrict__ W_gc,
                             const float* __restrict__ b_gc,
                             const float* __restrict__ W_lo,
                             const float* __restrict__ b_lo) {
    __shared__ float w0[64], w1[64], bi[64];
    __shared__ float A[6][64];
    int t = threadIdx.x;   // 64 threads
    if (t < 64) {
        w0[t] = W_in[t * 66 + 0];
        w1[t] = W_in[t * 66 + 1];
        bi[t] = b_in[t];
    }
    __syncthreads();
    if (t < 64) {
        float a0 = 0.f, a1 = 0.f, a2 = 0.f, a3 = 0.f, a4 = 0.f, a5 = 0.f;
        #pragma unroll 8
        for (int k = 0; k < 64; k++) {
            float g1 = W_gc[t * 128 + k];
            float g2 = W_gc[t * 128 + 64 + k];
            a0 = fmaf(g1, w0[k], a0);
            a1 = fmaf(g1, w1[k], a1);
            a5 = fmaf(g1, bi[k], a5);
            a2 = fmaf(g2, w0[k], a2);
            a3 = fmaf(g2, w1[k], a3);
            a4 = fmaf(g2, bi[k], a4);
        }
        A[0][t] = a0; A[1][t] = a1; A[2][t] = a2;
        A[3][t] = a3; A[4][t] = a4; A[5][t] = a5 + b_gc[t];
    }
    __syncthreads();
    if (t < 64) {
        float c0 = 0.f, c1 = 0.f, c2 = 0.f, c3 = 0.f, c4 = 0.f, c5 = 0.f;
        #pragma unroll 8
        for (int k = 0; k < 64; k++) {
            float wl = W_lo[t * 128 + k];   // first 64 cols only (rest hit h=0)
            c0 = fmaf(wl, A[0][k], c0);
            c1 = fmaf(wl, A[1][k], c1);
            c2 = fmaf(wl, A[2][k], c2);
            c3 = fmaf(wl, A[3][k], c3);
            c4 = fmaf(wl, A[4][k], c4);
            c5 = fmaf(wl, A[5][k], c5);
        }
        c5 += b_lo[t];
        g_C[0 * 64 + t] = c0; g_C[1 * 64 + t] = c1; g_C[2 * 64 + t] = c2;
        g_C[3 * 64 + t] = c3; g_C[4 * 64 + t] = c4; g_C[5 * 64 + t] = c5;
    }
    // zero colsum accumulator
    for (int i = t; i < Ndim; i += 64) g_cs[i] = 0.f;
}

// ---------------------------------------------------------------------------
// Kernel 2: column sums of adj.  grid(16) x 256 threads.
// block bx: m-range = (bx&3)*256, n-chunk = bx>>2 (256 rows each).
// ---------------------------------------------------------------------------
__global__ void colsum_kernel(const float* __restrict__ adj) {
    int m = (blockIdx.x & 3) * 256 + threadIdx.x;
    int n0 = (blockIdx.x >> 2) * 256;
    float s = 0.f;
    #pragma unroll 8
    for (int n = n0; n < n0 + 256; n++)
        s += adj[n * Ndim + m];
    atomicAdd(&g_cs[m], s);
}

// ---------------------------------------------------------------------------
// Kernel 3: S = adj^T * R  where R[n, j]:
//   j <  512: x1(b = j/64, n, t = j%64)   (built on the fly)
//   j >= 512: float(mask(b = (j-512)/64, n, t))
// S stored row-major [m][j].  Tiles 64x64, BK=16, 256 threads, 4x4 microtile.
// grid: (16 j-tiles, 16 m-tiles)
// ---------------------------------------------------------------------------
__global__ void gemm_kernel(const float* __restrict__ adj,
                            const float* __restrict__ x,
                            const int*   __restrict__ mask,
                            const float* __restrict__ b_fs) {
    __shared__ float As[16][64];
    __shared__ float Bs[16][64];

    const int tid = threadIdx.x;          // 256
    const int tx = tid & 15;              // j micro group
    const int ty = tid >> 4;              // m micro group
    const int m0 = blockIdx.y * 64;
    const int j0 = blockIdx.x * 64;
    const bool maskReg = (j0 >= NCOLS);
    const int  bcol = (maskReg ? (j0 - NCOLS) : j0) >> 6;  // batch of this tile
    const float bfs0 = b_fs[0];

    const int lk  = tid >> 4;             // 0..15 : k row to load
    const int lm4 = (tid & 15) << 2;      // 0..60 : 4-wide column offset

    float acc[4][4];
    #pragma unroll
    for (int i = 0; i < 4; i++)
        #pragma unroll
        for (int j = 0; j < 4; j++) acc[i][j] = 0.f;

    for (int k0 = 0; k0 < Ndim; k0 += 16) {
        // adj tile: As[k][m]  (m contiguous -> coalesced float4)
        float4 av = *(const float4*)&adj[(k0 + lk) * Ndim + m0 + lm4];
        *(float4*)&As[lk][lm4] = av;

        // R tile
        int n = k0 + lk;
        int g = bcol * (Ndim * Tdim) + n * Tdim + lm4;  // x/mask flat index
        int4 mk = *(const int4*)&mask[g];
        float4 bv;
        if (maskReg) {
            bv.x = (float)mk.x; bv.y = (float)mk.y;
            bv.z = (float)mk.z; bv.w = (float)mk.w;
        } else {
            float4 xv = *(const float4*)&x[g];
            bv.x = mk.x ? xv.x : bfs0;
            bv.y = mk.y ? xv.y : bfs0;
            bv.z = mk.z ? xv.z : bfs0;
            bv.w = mk.w ? xv.w : bfs0;
        }
        *(float4*)&Bs[lk][lm4] = bv;

        __syncthreads();

        #pragma unroll
        for (int k = 0; k < 16; k++) {
            float4 a = *(const float4*)&As[k][ty << 2];
            float4 b = *(const float4*)&Bs[k][tx << 2];
            acc[0][0] = fmaf(a.x, b.x, acc[0][0]);
            acc[0][1] = fmaf(a.x, b.y, acc[0][1]);
            acc[0][2] = fmaf(a.x, b.z, acc[0][2]);
            acc[0][3] = fmaf(a.x, b.w, acc[0][3]);
            acc[1][0] = fmaf(a.y, b.x, acc[1][0]);
            acc[1][1] = fmaf(a.y, b.y, acc[1][1]);
            acc[1][2] = fmaf(a.y, b.z, acc[1][2]);
            acc[1][3] = fmaf(a.y, b.w, acc[1][3]);
            acc[2][0] = fmaf(a.z, b.x, acc[2][0]);
            acc[2][1] = fmaf(a.z, b.y, acc[2][1]);
            acc[2][2] = fmaf(a.z, b.z, acc[2][2]);
            acc[2][3] = fmaf(a.z, b.w, acc[2][3]);
            acc[3][0] = fmaf(a.w, b.x, acc[3][0]);
            acc[3][1] = fmaf(a.w, b.y, acc[3][1]);
            acc[3][2] = fmaf(a.w, b.z, acc[3][2]);
            acc[3][3] = fmaf(a.w, b.w, acc[3][3]);
        }
        __syncthreads();
    }

    #pragma unroll
    for (int i = 0; i < 4; i++) {
        float4 st = make_float4(acc[i][0], acc[i][1], acc[i][2], acc[i][3]);
        *(float4*)&g_S[(m0 + (ty << 2) + i) * 1024 + j0 + (tx << 2)] = st;
    }
}

// ---------------------------------------------------------------------------
// Kernel 4: per-element tail.  grid 2048 x 256.
// ---------------------------------------------------------------------------
__global__ void final_kernel(const float* __restrict__ x,
                             const int*   __restrict__ mask,
                             const float* __restrict__ b_fs,
                             const float* __restrict__ prelu_a,
                             const float* __restrict__ W_ro,
                             const float* __restrict__ b_ro,
                             const float* __restrict__ W_o1,
                             const float* __restrict__ b_o1,
                             const float* __restrict__ W_o2,
                             const float* __restrict__ b_o2,
                             float* __restrict__ out) {
    __shared__ float sC[6][64], swro[64], swo1[64], sbo1[64], swo2[64];
    int t = threadIdx.x;
    if (t < 64) {
        #pragma unroll
        for (int i = 0; i < 6; i++) sC[i][t] = g_C[i * 64 + t];
        swro[t] = W_ro[t];      // first 64 cols; cols 64..127 hit h=0
        swo1[t] = W_o1[t];
        sbo1[t] = b_o1[t];
        swo2[t] = W_o2[t];
    }
    __syncthreads();

    int idx = blockIdx.x * blockDim.x + t;
    if (idx >= TOTAL) return;

    const float bfs0 = b_fs[0];
    const float a    = prelu_a[0];

    int   mi = mask[idx];
    float mF = (float)mi;
    float xv = x[idx];
    float x1 = mi ? xv : bfs0;

    int n  = (idx >> 6) & (Ndim - 1);
    int b  = idx >> 16;          // / (Ndim*Tdim)
    int tt = idx & 63;
    int j  = (b << 6) | tt;

    float s1 = g_S[n * 1024 + j];
    float s2 = g_S[n * 1024 + NCOLS + j];
    float cs = g_cs[n];

    float xs2 = b_ro[0];
    #pragma unroll
    for (int o = 0; o < 64; o++) {
        float v = sC[5][o];
        v = fmaf(sC[0][o], x1, v);
        v = fmaf(sC[1][o], mF, v);
        v = fmaf(sC[2][o], s1, v);
        v = fmaf(sC[3][o], s2, v);
        v = fmaf(sC[4][o], cs, v);
        float p = (v >= 0.f) ? v : a * v;
        xs2 = fmaf(swro[o], p, xs2);
    }

    float acc = b_o2[0];
    #pragma unroll
    for (int f = 0; f < 64; f++) {
        float y = fmaf(swo1[f], xs2, sbo1[f]);
        y = fmaxf(y, 0.f);
        acc = fmaf(swo2[f], y, acc);
    }
    out[idx] = acc;
}

// ---------------------------------------------------------------------------
extern "C" void kernel_launch(void* const* d_in, const int* in_sizes, int n_in,
                              void* d_out, int out_size) {
    const float* x     = (const float*)d_in[0];
    const int*   mask  = (const int*)  d_in[1];
    // d_in[2] = W_fs (unused: multiplies h=0)
    const float* b_fs  = (const float*)d_in[3];
    const float* W_in  = (const float*)d_in[4];
    const float* b_in  = (const float*)d_in[5];
    const float* adj   = (const float*)d_in[6];
    const float* W_gc  = (const float*)d_in[7];
    const float* b_gc  = (const float*)d_in[8];
    const float* W_lo  = (const float*)d_in[9];
    const float* b_lo  = (const float*)d_in[10];
    const float* pre_a = (const float*)d_in[11];
    const float* W_ro  = (const float*)d_in[12];
    const float* b_ro  = (const float*)d_in[13];
    const float* W_o1  = (const float*)d_in[14];
    const float* b_o1  = (const float*)d_in[15];
    const float* W_o2  = (const float*)d_in[16];
    const float* b_o2  = (const float*)d_in[17];
    float* out = (float*)d_out;

    coeff_kernel<<<1, 64>>>(W_in, b_in, W_gc, b_gc, W_lo, b_lo);
    colsum_kernel<<<16, 256>>>(adj);
    {
        dim3 grid(16, 16);
        gemm_kernel<<<grid, 256>>>(adj, x, mask, b_fs);
    }
    final_kernel<<<TOTAL / 256, 256>>>(x, mask, b_fs, pre_a, W_ro, b_ro,
                                       W_o1, b_o1, W_o2, b_o2, out);
}